// round 1
// baseline (speedup 1.0000x reference)
#include <cuda_runtime.h>

#define NLINKS 10000
#define NPATHS 100000
#define PLEN 8
#define NE (NPATHS*PLEN)
#define HD 32
#define G3 96
#define TROUNDS 8

typedef unsigned long long u64;

// ---------------- scratch (device globals; no allocation allowed) ----------------
__device__ __align__(16) float g_msgs[NE*HD];          // 102.4 MB, link-sorted hop messages
__device__ __align__(16) float g_link_state[NLINKS*HD];
__device__ __align__(16) float g_path_state[NPATHS*HD];
__device__ __align__(16) float g_gi[NLINKS*G3];        // per-round precomputed x@Wih^T + bih per link
__device__ int g_counts[NLINKS];
__device__ int g_offsets[NLINKS+1];
__device__ int g_pos[NE];

// ---------------- helpers ----------------
__device__ __forceinline__ float fsig(float x){ return __fdividef(1.f, 1.f + __expf(-x)); }
__device__ __forceinline__ float ftanh(float x){ return __fdividef(2.f, 1.f + __expf(-2.f*x)) - 1.f; }

__device__ __forceinline__ void fma2(u64 &acc, u64 a, u64 b){
    asm("fma.rn.f32x2 %0, %1, %2, %0;" : "+l"(acc) : "l"(a), "l"(b));
}
__device__ __forceinline__ float lo2(u64 v){ return __uint_as_float((unsigned)v); }
__device__ __forceinline__ float hi2(u64 v){ return __uint_as_float((unsigned)(v>>32)); }
__device__ __forceinline__ u64 pk2(float a, float b){
    u64 r; asm("mov.b64 %0, {%1, %2};" : "=l"(r) : "f"(a), "f"(b)); return r;
}

// ---------------- setup: counting sort of links -> CSR ----------------
__global__ void k_zero_counts(){
    int i = blockIdx.x*blockDim.x + threadIdx.x;
    if (i < NLINKS) g_counts[i] = 0;
}
__global__ void k_hist(const int* __restrict__ links){
    int e = blockIdx.x*blockDim.x + threadIdx.x;
    if (e < NE) atomicAdd(&g_counts[links[e]], 1);
}
__global__ void k_scan(){
    __shared__ int ssum[256];
    const int CH = (NLINKS + 255) / 256;   // 40
    int t = threadIdx.x;
    int base = t*CH;
    int s = 0;
    for (int i = 0; i < CH; i++){ int x = base+i; if (x < NLINKS) s += g_counts[x]; }
    ssum[t] = s;
    __syncthreads();
    if (t == 0){
        int run = 0;
        for (int i = 0; i < 256; i++){ int v = ssum[i]; ssum[i] = run; run += v; }
        g_offsets[NLINKS] = run;
    }
    __syncthreads();
    int run = ssum[t];
    for (int i = 0; i < CH; i++){
        int x = base+i;
        if (x < NLINKS){ g_offsets[x] = run; run += g_counts[x]; g_counts[x] = 0; }
    }
}
__global__ void k_pos(const int* __restrict__ links){
    int e = blockIdx.x*blockDim.x + threadIdx.x;
    if (e < NE){
        int l = links[e];
        g_pos[e] = g_offsets[l] + atomicAdd(&g_counts[l], 1);
    }
}
__global__ void k_init_links(const float* __restrict__ cap){
    int i = blockIdx.x*blockDim.x + threadIdx.x;
    if (i < NLINKS*HD) g_link_state[i] = (i & (HD-1)) ? 0.f : cap[i >> 5];
}
__global__ void k_init_paths(const float* __restrict__ bw){
    int i = blockIdx.x*blockDim.x + threadIdx.x;
    if (i < NPATHS*HD) g_path_state[i] = (i & (HD-1)) ? 0.f : bw[i >> 5];
}

// ---------------- per-round: precompute gi per link ----------------
__global__ void k_gi_kernel(const float* __restrict__ Wih, const float* __restrict__ bih){
    int idx = blockIdx.x*blockDim.x + threadIdx.x;
    if (idx >= NLINKS*G3) return;
    int l = idx / G3, j = idx - l*G3;
    const float* h = g_link_state + l*HD;
    const float* w = Wih + j*HD;
    float a = bih[j];
    #pragma unroll
    for (int k = 0; k < HD; k++) a += h[k] * __ldg(w + k);
    g_gi[idx] = a;
}

// ---------------- path GRU kernel: 8 steps, f32x2 packed FMAs ----------------
__global__ void __launch_bounds__(64, 6) k_path(const int* __restrict__ links,
        const float* __restrict__ pWhh, const float* __restrict__ pbhh)
{
    __shared__ __align__(16) float sW[G3*HD];   // Whh, row-major [96][32]
    __shared__ float sb[G3];                    // bhh
    __shared__ float sGi[2][32][97];            // staged gi rows per warp, padded
    for (int i = threadIdx.x; i < G3*HD; i += 64) sW[i] = pWhh[i];
    for (int i = threadIdx.x; i < G3;    i += 64) sb[i] = pbhh[i];
    __syncthreads();

    const int w = threadIdx.x >> 5, lane = threadIdx.x & 31;
    int wg = blockIdx.x*2 + w;
    if (wg >= NPATHS/32) return;                 // NPATHS % 32 == 0 -> warp-uniform
    const int p = wg*32 + lane;

    u64 h2[16];
    {
        const float4* hp = (const float4*)(g_path_state + p*HD);
        #pragma unroll
        for (int i = 0; i < 8; i++){
            float4 v = hp[i];
            h2[2*i] = pk2(v.x, v.y); h2[2*i+1] = pk2(v.z, v.w);
        }
    }
    int mylink[PLEN], mypos[PLEN];
    #pragma unroll
    for (int s = 0; s < PLEN; s++){
        mylink[s] = links[p*PLEN + s];
        mypos[s]  = g_pos[p*PLEN + s];
    }

    #pragma unroll 1
    for (int s = 0; s < PLEN; s++){
        // cooperative coalesced staging of this warp's 32 gi rows (96 floats each)
        int lnk = mylink[s];
        #pragma unroll
        for (int r = 0; r < 32; r++){
            int lr = __shfl_sync(0xffffffffu, lnk, r);
            const float* g = g_gi + lr*G3;
            sGi[w][r][lane]      = g[lane];
            sGi[w][r][lane + 32] = g[lane + 32];
            sGi[w][r][lane + 64] = g[lane + 64];
        }
        __syncwarp();

        float hn[32];
        const float* myg = sGi[w][lane];
        #pragma unroll
        for (int j = 0; j < 32; j++){
            u64 aR = 0ull, aZ = 0ull, aN = 0ull;
            const ulonglong2* wR = (const ulonglong2*)(sW + j*HD);
            const ulonglong2* wZ = (const ulonglong2*)(sW + (32+j)*HD);
            const ulonglong2* wN = (const ulonglong2*)(sW + (64+j)*HD);
            #pragma unroll
            for (int k = 0; k < 8; k++){
                ulonglong2 a = wR[k]; fma2(aR, h2[2*k], a.x); fma2(aR, h2[2*k+1], a.y);
                ulonglong2 b = wZ[k]; fma2(aZ, h2[2*k], b.x); fma2(aZ, h2[2*k+1], b.y);
                ulonglong2 c = wN[k]; fma2(aN, h2[2*k], c.x); fma2(aN, h2[2*k+1], c.y);
            }
            float ghr = lo2(aR) + hi2(aR) + sb[j];
            float ghz = lo2(aZ) + hi2(aZ) + sb[32+j];
            float ghn = lo2(aN) + hi2(aN) + sb[64+j];
            float rr = fsig(myg[j]      + ghr);
            float zz = fsig(myg[32 + j] + ghz);
            float nn = ftanh(myg[64 + j] + rr*ghn);
            float hj = (j & 1) ? hi2(h2[j >> 1]) : lo2(h2[j >> 1]);
            hn[j] = nn + zz*(hj - nn);
        }
        __syncwarp();   // done reading sGi before next stage overwrites

        #pragma unroll
        for (int i = 0; i < 16; i++) h2[i] = pk2(hn[2*i], hn[2*i+1]);
        float4* mp = (float4*)(g_msgs + mypos[s]*HD);
        #pragma unroll
        for (int i = 0; i < 8; i++)
            mp[i] = make_float4(hn[4*i], hn[4*i+1], hn[4*i+2], hn[4*i+3]);
    }

    float4* op = (float4*)(g_path_state + p*HD);
    #pragma unroll
    for (int i = 0; i < 8; i++)
        op[i] = make_float4(lo2(h2[2*i]), hi2(h2[2*i]), lo2(h2[2*i+1]), hi2(h2[2*i+1]));
}

// ---------------- link kernel: CSR segment-sum + link GRU ----------------
__global__ void __launch_bounds__(256) k_link(const float* __restrict__ Wih,
        const float* __restrict__ Whh, const float* __restrict__ bih,
        const float* __restrict__ bhh)
{
    __shared__ float sWi[HD*G3];   // transposed: [k][j]
    __shared__ float sWh[HD*G3];
    __shared__ float sbi[G3], sbh[G3];
    __shared__ float sAgg[8][33], sH[8][33];
    for (int i = threadIdx.x; i < HD*G3; i += 256){
        int j = i / HD, k = i - j*HD;
        sWi[k*G3 + j] = Wih[i];
        sWh[k*G3 + j] = Whh[i];
    }
    for (int i = threadIdx.x; i < G3; i += 256){ sbi[i] = bih[i]; sbh[i] = bhh[i]; }
    __syncthreads();

    int w = threadIdx.x >> 5, lane = threadIdx.x & 31;
    int l = blockIdx.x*8 + w;
    if (l >= NLINKS) return;

    int beg = g_offsets[l], end = g_offsets[l+1];
    float a0 = 0.f, a1 = 0.f, a2 = 0.f, a3 = 0.f;
    int i = beg;
    for (; i + 4 <= end; i += 4){
        a0 += g_msgs[(i  )*HD + lane];
        a1 += g_msgs[(i+1)*HD + lane];
        a2 += g_msgs[(i+2)*HD + lane];
        a3 += g_msgs[(i+3)*HD + lane];
    }
    for (; i < end; i++) a0 += g_msgs[i*HD + lane];
    float acc = (a0 + a1) + (a2 + a3);

    sAgg[w][lane] = acc;
    sH[w][lane]   = g_link_state[l*HD + lane];
    __syncwarp();

    int j = lane;
    float xr = sbi[j], xz = sbi[32+j], xn = sbi[64+j];
    float hr = sbh[j], hz = sbh[32+j], hnv = sbh[64+j];
    #pragma unroll
    for (int k = 0; k < HD; k++){
        float av = sAgg[w][k], hh = sH[w][k];
        xr  += av*sWi[k*G3 + j];
        xz  += av*sWi[k*G3 + 32 + j];
        xn  += av*sWi[k*G3 + 64 + j];
        hr  += hh*sWh[k*G3 + j];
        hz  += hh*sWh[k*G3 + 32 + j];
        hnv += hh*sWh[k*G3 + 64 + j];
    }
    float rr = fsig(xr + hr);
    float zz = fsig(xz + hz);
    float nn = ftanh(xn + rr*hnv);
    float hj = sH[w][j];
    g_link_state[l*HD + j] = nn + zz*(hj - nn);
}

// ---------------- readout MLP ----------------
__global__ void k_read(const float* __restrict__ W1, const float* __restrict__ b1,
                       const float* __restrict__ W2, const float* __restrict__ b2,
                       const float* __restrict__ W3, const float* __restrict__ b3,
                       float* __restrict__ out)
{
    int p = blockIdx.x*blockDim.x + threadIdx.x;
    if (p >= NPATHS) return;
    float h[HD];
    const float4* hp = (const float4*)(g_path_state + p*HD);
    #pragma unroll
    for (int i = 0; i < 8; i++){
        float4 v = hp[i];
        h[4*i] = v.x; h[4*i+1] = v.y; h[4*i+2] = v.z; h[4*i+3] = v.w;
    }
    float x1[8];
    #pragma unroll
    for (int j = 0; j < 8; j++){
        float a = __ldg(b1 + j);
        #pragma unroll
        for (int k = 0; k < HD; k++) a += __ldg(W1 + j*HD + k) * h[k];
        x1[j] = fmaxf(a, 0.f);
    }
    float x2[8];
    #pragma unroll
    for (int j = 0; j < 8; j++){
        float a = __ldg(b2 + j);
        #pragma unroll
        for (int k = 0; k < 8; k++) a += __ldg(W2 + j*8 + k) * x1[k];
        x2[j] = fmaxf(a, 0.f);
    }
    float o = __ldg(b3);
    #pragma unroll
    for (int k = 0; k < 8; k++) o += __ldg(W3 + k) * x2[k];
    out[p] = o;
}

// ---------------- launch ----------------
extern "C" void kernel_launch(void* const* d_in, const int* in_sizes, int n_in,
                              void* d_out, int out_size)
{
    const int*   links = (const int*)  d_in[0];
    const float* cap   = (const float*)d_in[3];
    const float* bw    = (const float*)d_in[4];
    const float* pWih  = (const float*)d_in[5];
    const float* pWhh  = (const float*)d_in[6];
    const float* pbih  = (const float*)d_in[7];
    const float* pbhh  = (const float*)d_in[8];
    const float* lWih  = (const float*)d_in[9];
    const float* lWhh  = (const float*)d_in[10];
    const float* lbih  = (const float*)d_in[11];
    const float* lbhh  = (const float*)d_in[12];
    const float* W1    = (const float*)d_in[13];
    const float* b1    = (const float*)d_in[14];
    const float* W2    = (const float*)d_in[15];
    const float* b2    = (const float*)d_in[16];
    const float* W3    = (const float*)d_in[17];
    const float* b3    = (const float*)d_in[18];
    float* out = (float*)d_out;

    // counting sort (CSR) of hop entries by link, recomputed each call
    k_zero_counts<<<(NLINKS + 255)/256, 256>>>();
    k_hist<<<(NE + 255)/256, 256>>>(links);
    k_scan<<<1, 256>>>();
    k_pos<<<(NE + 255)/256, 256>>>(links);
    k_init_links<<<(NLINKS*HD + 255)/256, 256>>>(cap);
    k_init_paths<<<(NPATHS*HD + 255)/256, 256>>>(bw);

    const int nwarps = NPATHS/32;                 // 3125
    const int path_grid = (nwarps + 1)/2;         // 2 warps per 64-thread block
    for (int t = 0; t < TROUNDS; t++){
        k_gi_kernel<<<(NLINKS*G3 + 127)/128, 128>>>(pWih, pbih);
        k_path<<<path_grid, 64>>>(links, pWhh, pbhh);
        k_link<<<(NLINKS + 7)/8, 256>>>(lWih, lWhh, lbih, lbhh);
    }
    k_read<<<(NPATHS + 127)/128, 128>>>(W1, b1, W2, b2, W3, b3, out);
}

// round 5
// speedup vs baseline: 1.2893x; 1.2893x over previous
#include <cuda_runtime.h>

#define NLINKS 10000
#define NPATHS 100000
#define PLEN 8
#define NE (NPATHS*PLEN)
#define HD 32
#define G3 96
#define TROUNDS 8

typedef unsigned long long u64;

// ---------------- scratch (device globals; no allocation allowed) ----------------
__device__ __align__(16) float g_msgs[NE*HD];          // 102.4 MB, link-sorted hop messages
__device__ __align__(16) float g_link_state[NLINKS*HD];
__device__ __align__(16) float g_path_state[NPATHS*HD];
__device__ __align__(16) float g_gi[NLINKS*G3];        // per-round precomputed x@Wih^T + bih per link
__device__ int g_counts[NLINKS];
__device__ int g_offsets[NLINKS+1];
__device__ int g_pos[NE];

// ---------------- helpers ----------------
__device__ __forceinline__ float fsig(float x){ return __fdividef(1.f, 1.f + __expf(-x)); }
__device__ __forceinline__ float ftanh(float x){ return __fdividef(2.f, 1.f + __expf(-2.f*x)) - 1.f; }

__device__ __forceinline__ void fma2(u64 &acc, u64 a, u64 b){
    asm("fma.rn.f32x2 %0, %1, %2, %0;" : "+l"(acc) : "l"(a), "l"(b));
}
__device__ __forceinline__ float lo2(u64 v){ return __uint_as_float((unsigned)v); }
__device__ __forceinline__ float hi2(u64 v){ return __uint_as_float((unsigned)(v>>32)); }
__device__ __forceinline__ u64 pk2(float a, float b){
    u64 r; asm("mov.b64 %0, {%1, %2};" : "=l"(r) : "f"(a), "f"(b)); return r;
}

// ---------------- setup: counting sort of links -> CSR ----------------
__global__ void k_zero_counts(){
    int i = blockIdx.x*blockDim.x + threadIdx.x;
    if (i < NLINKS) g_counts[i] = 0;
}
__global__ void k_hist(const int* __restrict__ links){
    int e = blockIdx.x*blockDim.x + threadIdx.x;
    if (e < NE) atomicAdd(&g_counts[links[e]], 1);
}
__global__ void k_scan(){
    __shared__ int ssum[256];
    const int CH = (NLINKS + 255) / 256;   // 40
    int t = threadIdx.x;
    int base = t*CH;
    int s = 0;
    for (int i = 0; i < CH; i++){ int x = base+i; if (x < NLINKS) s += g_counts[x]; }
    ssum[t] = s;
    __syncthreads();
    if (t == 0){
        int run = 0;
        for (int i = 0; i < 256; i++){ int v = ssum[i]; ssum[i] = run; run += v; }
        g_offsets[NLINKS] = run;
    }
    __syncthreads();
    int run = ssum[t];
    for (int i = 0; i < CH; i++){
        int x = base+i;
        if (x < NLINKS){ g_offsets[x] = run; run += g_counts[x]; g_counts[x] = 0; }
    }
}
// fused: per-edge slot assignment + state inits (single launch)
__global__ void k_setup(const int* __restrict__ links,
                        const float* __restrict__ cap,
                        const float* __restrict__ bw)
{
    int i = blockIdx.x*blockDim.x + threadIdx.x;
    if (i < NE){
        int l = links[i];
        g_pos[i] = g_offsets[l] + atomicAdd(&g_counts[l], 1);
    }
    if (i < NLINKS*HD) g_link_state[i] = (i & (HD-1)) ? 0.f : cap[i >> 5];
    if (i < NPATHS*HD) g_path_state[i] = (i & (HD-1)) ? 0.f : bw[i >> 5];
}

// ---------------- round-0 gi: coalesced, shared transposed weights ----------------
__global__ void __launch_bounds__(192) k_gi(const float* __restrict__ Wih,
                                            const float* __restrict__ bih)
{
    __shared__ float sWT[HD*G3];   // [k][j]
    __shared__ float sB[G3];
    for (int i = threadIdx.x; i < HD*G3; i += 192){
        int j = i >> 5, k = i & 31;
        sWT[k*G3 + j] = Wih[i];
    }
    for (int i = threadIdx.x; i < G3; i += 192) sB[i] = bih[i];
    __syncthreads();

    int lgrp = threadIdx.x / G3;          // 0..1 (warp-uniform: warps are 32-aligned in j)
    int j = threadIdx.x - lgrp*G3;
    for (int l0 = blockIdx.x*2; l0 < NLINKS; l0 += gridDim.x*2){
        int l = l0 + lgrp;
        if (l < NLINKS){
            const float* h = g_link_state + l*HD;
            float a = sB[j];
            #pragma unroll
            for (int k = 0; k < HD; k++) a += __ldg(h + k) * sWT[k*G3 + j];
            g_gi[l*G3 + j] = a;
        }
    }
}

// ---------------- path GRU kernel: 8 steps, f32x2 packed FMAs ----------------
template<bool WRITE_MSGS>
__global__ void __launch_bounds__(128, 3) k_path(const int* __restrict__ links,
        const float* __restrict__ pWhh, const float* __restrict__ pbhh)
{
    __shared__ __align__(16) float sW[G3*HD];   // Whh, row-major [96][32]
    __shared__ float sb[G3];                    // bhh
    __shared__ float sGi[4][32][97];            // staged gi rows per warp, padded
    for (int i = threadIdx.x; i < G3*HD; i += 128) sW[i] = pWhh[i];
    for (int i = threadIdx.x; i < G3;    i += 128) sb[i] = pbhh[i];
    __syncthreads();

    const int w = threadIdx.x >> 5, lane = threadIdx.x & 31;
    int wg = blockIdx.x*4 + w;
    if (wg >= NPATHS/32) return;                 // warp-uniform exit
    const int p = wg*32 + lane;

    u64 h2[16], h2n[16];
    {
        const float4* hp = (const float4*)(g_path_state + p*HD);
        #pragma unroll
        for (int i = 0; i < 8; i++){
            float4 v = hp[i];
            h2[2*i] = pk2(v.x, v.y); h2[2*i+1] = pk2(v.z, v.w);
        }
    }
    int mylink[PLEN], mypos[PLEN];
    #pragma unroll
    for (int s = 0; s < PLEN; s++){
        mylink[s] = links[p*PLEN + s];
        if (WRITE_MSGS) mypos[s] = g_pos[p*PLEN + s];
    }

    const float* myg = sGi[w][lane];
    #pragma unroll 1
    for (int s = 0; s < PLEN; s++){
        // cooperative coalesced staging of this warp's 32 gi rows (96 floats each)
        int lnk = mylink[s];
        #pragma unroll
        for (int r = 0; r < 32; r++){
            int lr = __shfl_sync(0xffffffffu, lnk, r);
            const float* g = g_gi + lr*G3;
            sGi[w][r][lane]      = g[lane];
            sGi[w][r][lane + 32] = g[lane + 32];
            sGi[w][r][lane + 64] = g[lane + 64];
        }
        __syncwarp();

        #pragma unroll 4
        for (int j2 = 0; j2 < 16; j2++){
            const int j0 = 2*j2, j1 = j0 + 1;
            u64 aR0=0ull, aR1=0ull, aZ0=0ull, aZ1=0ull, aN0=0ull, aN1=0ull;
            const ulonglong2* wR0 = (const ulonglong2*)(sW + j0*HD);
            const ulonglong2* wR1 = (const ulonglong2*)(sW + j1*HD);
            const ulonglong2* wZ0 = (const ulonglong2*)(sW + (32+j0)*HD);
            const ulonglong2* wZ1 = (const ulonglong2*)(sW + (32+j1)*HD);
            const ulonglong2* wN0 = (const ulonglong2*)(sW + (64+j0)*HD);
            const ulonglong2* wN1 = (const ulonglong2*)(sW + (64+j1)*HD);
            #pragma unroll
            for (int k = 0; k < 8; k++){
                u64 ha = h2[2*k], hb = h2[2*k+1];
                ulonglong2 a = wR0[k]; fma2(aR0, ha, a.x); fma2(aR0, hb, a.y);
                ulonglong2 b = wR1[k]; fma2(aR1, ha, b.x); fma2(aR1, hb, b.y);
                ulonglong2 c = wZ0[k]; fma2(aZ0, ha, c.x); fma2(aZ0, hb, c.y);
                ulonglong2 d = wZ1[k]; fma2(aZ1, ha, d.x); fma2(aZ1, hb, d.y);
                ulonglong2 e = wN0[k]; fma2(aN0, ha, e.x); fma2(aN0, hb, e.y);
                ulonglong2 f = wN1[k]; fma2(aN1, ha, f.x); fma2(aN1, hb, f.y);
            }
            float ghr0 = lo2(aR0) + hi2(aR0) + sb[j0];
            float ghr1 = lo2(aR1) + hi2(aR1) + sb[j1];
            float ghz0 = lo2(aZ0) + hi2(aZ0) + sb[32+j0];
            float ghz1 = lo2(aZ1) + hi2(aZ1) + sb[32+j1];
            float ghn0 = lo2(aN0) + hi2(aN0) + sb[64+j0];
            float ghn1 = lo2(aN1) + hi2(aN1) + sb[64+j1];
            float r0 = fsig(myg[j0]    + ghr0);
            float r1 = fsig(myg[j1]    + ghr1);
            float z0 = fsig(myg[32+j0] + ghz0);
            float z1 = fsig(myg[32+j1] + ghz1);
            float n0 = ftanh(myg[64+j0] + r0*ghn0);
            float n1 = ftanh(myg[64+j1] + r1*ghn1);
            float h0 = lo2(h2[j2]), h1 = hi2(h2[j2]);
            h2n[j2] = pk2(n0 + z0*(h0 - n0), n1 + z1*(h1 - n1));
        }
        __syncwarp();   // done reading sGi before next stage overwrites

        if (WRITE_MSGS){
            ulonglong2* mp = (ulonglong2*)(g_msgs + (size_t)mypos[s]*HD);
            #pragma unroll
            for (int i = 0; i < 8; i++){
                ulonglong2 v; v.x = h2n[2*i]; v.y = h2n[2*i+1];
                mp[i] = v;
            }
        }
        #pragma unroll
        for (int i = 0; i < 16; i++) h2[i] = h2n[i];
    }

    ulonglong2* op = (ulonglong2*)(g_path_state + p*HD);
    #pragma unroll
    for (int i = 0; i < 8; i++){
        ulonglong2 v; v.x = h2[2*i]; v.y = h2[2*i+1];
        op[i] = v;
    }
}

// ---------------- link kernel: CSR segment-sum + link GRU + next-round gi ----------------
__global__ void __launch_bounds__(256) k_linkgi(const float* __restrict__ Wih,
        const float* __restrict__ Whh, const float* __restrict__ bih,
        const float* __restrict__ bhh,
        const float* __restrict__ pWih, const float* __restrict__ pbih)
{
    __shared__ float sWi[HD*G3];    // link Wih, transposed [k][j]
    __shared__ float sWh[HD*G3];    // link Whh, transposed [k][j]
    __shared__ float sPWT[HD*G3];   // path Wih, transposed [k][j]
    __shared__ float sbi[G3], sbh[G3], sPB[G3];
    __shared__ float sAgg[8][33], sH[8][33], sH2[8][33];
    for (int i = threadIdx.x; i < HD*G3; i += 256){
        int j = i >> 5, k = i & 31;
        sWi[k*G3 + j]  = Wih[i];
        sWh[k*G3 + j]  = Whh[i];
        sPWT[k*G3 + j] = pWih[i];
    }
    for (int i = threadIdx.x; i < G3; i += 256){
        sbi[i] = bih[i]; sbh[i] = bhh[i]; sPB[i] = pbih[i];
    }
    __syncthreads();

    int w = threadIdx.x >> 5, lane = threadIdx.x & 31;
    int l = blockIdx.x*8 + w;
    if (l >= NLINKS) return;

    int beg = g_offsets[l], end = g_offsets[l+1];
    float a0 = 0.f, a1 = 0.f, a2 = 0.f, a3 = 0.f;
    int i = beg;
    for (; i + 4 <= end; i += 4){
        a0 += g_msgs[(size_t)(i  )*HD + lane];
        a1 += g_msgs[(size_t)(i+1)*HD + lane];
        a2 += g_msgs[(size_t)(i+2)*HD + lane];
        a3 += g_msgs[(size_t)(i+3)*HD + lane];
    }
    for (; i < end; i++) a0 += g_msgs[(size_t)i*HD + lane];
    float acc = (a0 + a1) + (a2 + a3);

    sAgg[w][lane] = acc;
    sH[w][lane]   = g_link_state[l*HD + lane];
    __syncwarp();

    int j = lane;
    float xr = sbi[j], xz = sbi[32+j], xn = sbi[64+j];
    float hr = sbh[j], hz = sbh[32+j], hnv = sbh[64+j];
    #pragma unroll
    for (int k = 0; k < HD; k++){
        float av = sAgg[w][k], hh = sH[w][k];
        xr  += av*sWi[k*G3 + j];
        xz  += av*sWi[k*G3 + 32 + j];
        xn  += av*sWi[k*G3 + 64 + j];
        hr  += hh*sWh[k*G3 + j];
        hz  += hh*sWh[k*G3 + 32 + j];
        hnv += hh*sWh[k*G3 + 64 + j];
    }
    float rr = fsig(xr + hr);
    float zz = fsig(xz + hz);
    float nn = ftanh(xn + rr*hnv);
    float hj = sH[w][j];
    float hnew = nn + zz*(hj - nn);
    g_link_state[l*HD + j] = hnew;

    // next-round path-GRU input transform: gi = hnew @ pWih^T + pbih
    sH2[w][lane] = hnew;
    __syncwarp();
    float g0 = sPB[j], g1 = sPB[32+j], g2 = sPB[64+j];
    #pragma unroll
    for (int k = 0; k < HD; k++){
        float hv = sH2[w][k];
        g0 += hv*sPWT[k*G3 + j];
        g1 += hv*sPWT[k*G3 + 32 + j];
        g2 += hv*sPWT[k*G3 + 64 + j];
    }
    g_gi[l*G3 + j]      = g0;
    g_gi[l*G3 + 32 + j] = g1;
    g_gi[l*G3 + 64 + j] = g2;
}

// ---------------- readout MLP ----------------
__global__ void k_read(const float* __restrict__ W1, const float* __restrict__ b1,
                       const float* __restrict__ W2, const float* __restrict__ b2,
                       const float* __restrict__ W3, const float* __restrict__ b3,
                       float* __restrict__ out)
{
    int p = blockIdx.x*blockDim.x + threadIdx.x;
    if (p >= NPATHS) return;
    float h[HD];
    const float4* hp = (const float4*)(g_path_state + p*HD);
    #pragma unroll
    for (int i = 0; i < 8; i++){
        float4 v = hp[i];
        h[4*i] = v.x; h[4*i+1] = v.y; h[4*i+2] = v.z; h[4*i+3] = v.w;
    }
    float x1[8];
    #pragma unroll
    for (int j = 0; j < 8; j++){
        float a = __ldg(b1 + j);
        #pragma unroll
        for (int k = 0; k < HD; k++) a += __ldg(W1 + j*HD + k) * h[k];
        x1[j] = fmaxf(a, 0.f);
    }
    float x2[8];
    #pragma unroll
    for (int j = 0; j < 8; j++){
        float a = __ldg(b2 + j);
        #pragma unroll
        for (int k = 0; k < 8; k++) a += __ldg(W2 + j*8 + k) * x1[k];
        x2[j] = fmaxf(a, 0.f);
    }
    float o = __ldg(b3);
    #pragma unroll
    for (int k = 0; k < 8; k++) o += __ldg(W3 + k) * x2[k];
    out[p] = o;
}

// ---------------- launch ----------------
extern "C" void kernel_launch(void* const* d_in, const int* in_sizes, int n_in,
                              void* d_out, int out_size)
{
    const int*   links = (const int*)  d_in[0];
    const float* cap   = (const float*)d_in[3];
    const float* bw    = (const float*)d_in[4];
    const float* pWih  = (const float*)d_in[5];
    const float* pWhh  = (const float*)d_in[6];
    const float* pbih  = (const float*)d_in[7];
    const float* pbhh  = (const float*)d_in[8];
    const float* lWih  = (const float*)d_in[9];
    const float* lWhh  = (const float*)d_in[10];
    const float* lbih  = (const float*)d_in[11];
    const float* lbhh  = (const float*)d_in[12];
    const float* W1    = (const float*)d_in[13];
    const float* b1    = (const float*)d_in[14];
    const float* W2    = (const float*)d_in[15];
    const float* b2    = (const float*)d_in[16];
    const float* W3    = (const float*)d_in[17];
    const float* b3    = (const float*)d_in[18];
    float* out = (float*)d_out;

    // launches 1-5: CSR sort of hop->link, state init, round-0 gi
    k_zero_counts<<<(NLINKS + 255)/256, 256>>>();
    k_hist<<<(NE + 255)/256, 256>>>(links);
    k_scan<<<1, 256>>>();
    k_setup<<<(NPATHS*HD + 255)/256, 256>>>(links, cap, bw);
    k_gi<<<256, 192>>>(pWih, pbih);

    const int nwarps = NPATHS/32;                 // 3125
    const int path_grid = (nwarps + 3)/4;         // 4 warps per 128-thread block
    // launch 6 = first k_path (ncu -s 5 -c 1 captures this one)
    for (int t = 0; t < TROUNDS - 1; t++){
        k_path<true><<<path_grid, 128>>>(links, pWhh, pbhh);
        k_linkgi<<<(NLINKS + 7)/8, 256>>>(lWih, lWhh, lbih, lbhh, pWih, pbih);
    }
    k_path<false><<<path_grid, 128>>>(links, pWhh, pbhh);
    k_read<<<(NPATHS + 127)/128, 128>>>(W1, b1, W2, b2, W3, b3, out);
}

// round 8
// speedup vs baseline: 1.4779x; 1.1463x over previous
#include <cuda_runtime.h>
#include <cuda_fp16.h>

#define NLINKS 10000
#define NPATHS 100000
#define PLEN 8
#define NE (NPATHS*PLEN)
#define HD 32
#define G3 96
#define TROUNDS 8

typedef unsigned long long u64;

// ---------------- scratch (device globals; no allocation allowed) ----------------
__device__ __align__(16) __half g_msgs[NE*HD];         // 51.2 MB, link-sorted hop messages (fp16)
__device__ __align__(16) float g_link_state[NLINKS*HD];
__device__ __align__(16) float g_path_state[NPATHS*HD];
__device__ __align__(16) float g_gi[NLINKS*G3];        // per-round precomputed x@Wih^T + bih per link
__device__ int g_counts[NLINKS];      // invariant: ==0 on kernel_launch entry (BSS init; k_linkgi restores)
__device__ int g_offsets[NLINKS+1];
__device__ int g_pos[NE];

// ---------------- helpers ----------------
__device__ __forceinline__ float fsig(float x){ return __fdividef(1.f, 1.f + __expf(-x)); }
__device__ __forceinline__ float ftanh(float x){ return __fdividef(2.f, 1.f + __expf(-2.f*x)) - 1.f; }

__device__ __forceinline__ void fma2(u64 &acc, u64 a, u64 b){
    asm("fma.rn.f32x2 %0, %1, %2, %0;" : "+l"(acc) : "l"(a), "l"(b));
}
__device__ __forceinline__ float lo2(u64 v){ return __uint_as_float((unsigned)v); }
__device__ __forceinline__ float hi2(u64 v){ return __uint_as_float((unsigned)(v>>32)); }
__device__ __forceinline__ u64 pk2(float a, float b){
    u64 r; asm("mov.b64 %0, {%1, %2};" : "=l"(r) : "f"(a), "f"(b)); return r;
}

// ---------------- setup: counting sort of links -> CSR ----------------
__global__ void k_hist(const int* __restrict__ links){
    int e = blockIdx.x*blockDim.x + threadIdx.x;
    if (e < NE) atomicAdd(&g_counts[links[e]], 1);
}
__global__ void k_scan(){
    __shared__ int ssum[256];
    const int CH = (NLINKS + 255) / 256;   // 40
    int t = threadIdx.x;
    int base = t*CH;
    int s = 0;
    for (int i = 0; i < CH; i++){ int x = base+i; if (x < NLINKS) s += g_counts[x]; }
    ssum[t] = s;
    __syncthreads();
    if (t == 0){
        int run = 0;
        for (int i = 0; i < 256; i++){ int v = ssum[i]; ssum[i] = run; run += v; }
        g_offsets[NLINKS] = run;
    }
    __syncthreads();
    int run = ssum[t];
    for (int i = 0; i < CH; i++){
        int x = base+i;
        if (x < NLINKS){ g_offsets[x] = run; run += g_counts[x]; g_counts[x] = 0; }
    }
}
__global__ void k_pos(const int* __restrict__ links){
    int e = blockIdx.x*blockDim.x + threadIdx.x;
    if (e < NE){
        int l = links[e];
        g_pos[e] = g_offsets[l] + atomicAdd(&g_counts[l], 1);
    }
}

// ---------------- path GRU kernel: 8 steps, f32x2 packed FMAs ----------------
// FIRST: round 0 — path hidden init = [bw,0..], gi computed inline from cap (no g_gi read).
// WRITE: write per-hop messages (skipped on the last round; they'd never be consumed).
template<bool FIRST, bool WRITE>
__global__ void __launch_bounds__(128, 3) k_path(const int* __restrict__ links,
        const float* __restrict__ pWhh, const float* __restrict__ pbhh,
        const float* __restrict__ pWih, const float* __restrict__ pbih,
        const float* __restrict__ cap, const float* __restrict__ bw)
{
    __shared__ __align__(16) float sW[G3*HD];   // Whh, row-major [96][32]
    __shared__ float sb[G3];                    // bhh
    __shared__ float sW0[G3], sB0[G3];          // round-0 inline gi: Wih col0 + bih
    __shared__ float sGi[4][32][97];            // staged gi rows per warp, padded
    for (int i = threadIdx.x; i < G3*HD; i += 128) sW[i] = pWhh[i];
    for (int i = threadIdx.x; i < G3;    i += 128){
        sb[i] = pbhh[i];
        if (FIRST){ sW0[i] = pWih[i*HD]; sB0[i] = pbih[i]; }
    }
    __syncthreads();

    const int w = threadIdx.x >> 5, lane = threadIdx.x & 31;
    int wg = blockIdx.x*4 + w;
    if (wg >= NPATHS/32) return;                 // warp-uniform exit
    const int p = wg*32 + lane;

    u64 h2[16], h2n[16];
    if (FIRST){
        h2[0] = pk2(__ldg(bw + p), 0.f);
        #pragma unroll
        for (int i = 1; i < 16; i++) h2[i] = 0ull;
    } else {
        const float4* hp = (const float4*)(g_path_state + p*HD);
        #pragma unroll
        for (int i = 0; i < 8; i++){
            float4 v = hp[i];
            h2[2*i] = pk2(v.x, v.y); h2[2*i+1] = pk2(v.z, v.w);
        }
    }
    int mylink[PLEN], mypos[PLEN];
    {
        const int4* lp = (const int4*)(links + p*PLEN);
        int4 a = lp[0], b = lp[1];
        mylink[0]=a.x; mylink[1]=a.y; mylink[2]=a.z; mylink[3]=a.w;
        mylink[4]=b.x; mylink[5]=b.y; mylink[6]=b.z; mylink[7]=b.w;
        if (WRITE){
            const int4* pp = (const int4*)(g_pos + p*PLEN);
            int4 c = pp[0], d = pp[1];
            mypos[0]=c.x; mypos[1]=c.y; mypos[2]=c.z; mypos[3]=c.w;
            mypos[4]=d.x; mypos[5]=d.y; mypos[6]=d.z; mypos[7]=d.w;
        }
    }

    const float* myg = sGi[w][lane];
    #pragma unroll 1
    for (int s = 0; s < PLEN; s++){
        int lnk = mylink[s];
        float mycap = 0.f;
        if (FIRST){
            mycap = __ldg(cap + lnk);
        } else {
            // cooperative coalesced staging of this warp's 32 gi rows (96 floats each)
            #pragma unroll
            for (int r = 0; r < 32; r++){
                int lr = __shfl_sync(0xffffffffu, lnk, r);
                const float* g = g_gi + lr*G3;
                sGi[w][r][lane]      = g[lane];
                sGi[w][r][lane + 32] = g[lane + 32];
                sGi[w][r][lane + 64] = g[lane + 64];
            }
            __syncwarp();
        }

        #define GIX(x) (FIRST ? __fmaf_rn(mycap, sW0[x], sB0[x]) : myg[x])
        #pragma unroll 4
        for (int j2 = 0; j2 < 16; j2++){
            const int j0 = 2*j2, j1 = j0 + 1;
            u64 aR0=0ull, aR1=0ull, aZ0=0ull, aZ1=0ull, aN0=0ull, aN1=0ull;
            const ulonglong2* wR0 = (const ulonglong2*)(sW + j0*HD);
            const ulonglong2* wR1 = (const ulonglong2*)(sW + j1*HD);
            const ulonglong2* wZ0 = (const ulonglong2*)(sW + (32+j0)*HD);
            const ulonglong2* wZ1 = (const ulonglong2*)(sW + (32+j1)*HD);
            const ulonglong2* wN0 = (const ulonglong2*)(sW + (64+j0)*HD);
            const ulonglong2* wN1 = (const ulonglong2*)(sW + (64+j1)*HD);
            #pragma unroll
            for (int k = 0; k < 8; k++){
                u64 ha = h2[2*k], hb = h2[2*k+1];
                ulonglong2 a = wR0[k]; fma2(aR0, ha, a.x); fma2(aR0, hb, a.y);
                ulonglong2 b = wR1[k]; fma2(aR1, ha, b.x); fma2(aR1, hb, b.y);
                ulonglong2 c = wZ0[k]; fma2(aZ0, ha, c.x); fma2(aZ0, hb, c.y);
                ulonglong2 d = wZ1[k]; fma2(aZ1, ha, d.x); fma2(aZ1, hb, d.y);
                ulonglong2 e = wN0[k]; fma2(aN0, ha, e.x); fma2(aN0, hb, e.y);
                ulonglong2 f = wN1[k]; fma2(aN1, ha, f.x); fma2(aN1, hb, f.y);
            }
            float ghr0 = lo2(aR0) + hi2(aR0) + sb[j0];
            float ghr1 = lo2(aR1) + hi2(aR1) + sb[j1];
            float ghz0 = lo2(aZ0) + hi2(aZ0) + sb[32+j0];
            float ghz1 = lo2(aZ1) + hi2(aZ1) + sb[32+j1];
            float ghn0 = lo2(aN0) + hi2(aN0) + sb[64+j0];
            float ghn1 = lo2(aN1) + hi2(aN1) + sb[64+j1];
            float r0 = fsig(GIX(j0)    + ghr0);
            float r1 = fsig(GIX(j1)    + ghr1);
            float z0 = fsig(GIX(32+j0) + ghz0);
            float z1 = fsig(GIX(32+j1) + ghz1);
            float n0 = ftanh(GIX(64+j0) + r0*ghn0);
            float n1 = ftanh(GIX(64+j1) + r1*ghn1);
            float h0 = lo2(h2[j2]), h1 = hi2(h2[j2]);
            h2n[j2] = pk2(n0 + z0*(h0 - n0), n1 + z1*(h1 - n1));
        }
        #undef GIX
        if (!FIRST) __syncwarp();   // done reading sGi before next stage overwrites

        if (WRITE){
            union { __half2 h[16]; uint4 v[4]; } mu;
            #pragma unroll
            for (int i = 0; i < 16; i++)
                mu.h[i] = __floats2half2_rn(lo2(h2n[i]), hi2(h2n[i]));
            uint4* mp = (uint4*)(g_msgs + (size_t)mypos[s]*HD);
            #pragma unroll
            for (int i = 0; i < 4; i++) mp[i] = mu.v[i];
        }
        #pragma unroll
        for (int i = 0; i < 16; i++) h2[i] = h2n[i];
    }

    ulonglong2* op = (ulonglong2*)(g_path_state + p*HD);
    #pragma unroll
    for (int i = 0; i < 8; i++){
        ulonglong2 v; v.x = h2[2*i]; v.y = h2[2*i+1];
        op[i] = v;
    }
}

// ---------------- link kernel: CSR segment-sum (fp16 msgs) + link GRU + next-round gi ----------------
template<bool FIRST>
__global__ void __launch_bounds__(256) k_linkgi(const float* __restrict__ Wih,
        const float* __restrict__ Whh, const float* __restrict__ bih,
        const float* __restrict__ bhh,
        const float* __restrict__ pWih, const float* __restrict__ pbih,
        const float* __restrict__ cap)
{
    __shared__ float sWi[HD*G3];    // link Wih, transposed [k][j]
    __shared__ float sWh[HD*G3];    // link Whh, transposed [k][j]
    __shared__ float sPWT[HD*G3];   // path Wih, transposed [k][j]
    __shared__ float sbi[G3], sbh[G3], sPB[G3];
    __shared__ float sAgg[8][33], sH[8][33], sH2[8][33];
    for (int i = threadIdx.x; i < HD*G3; i += 256){
        int j = i >> 5, k = i & 31;
        sWi[k*G3 + j]  = Wih[i];
        sWh[k*G3 + j]  = Whh[i];
        sPWT[k*G3 + j] = pWih[i];
    }
    for (int i = threadIdx.x; i < G3; i += 256){
        sbi[i] = bih[i]; sbh[i] = bhh[i]; sPB[i] = pbih[i];
    }
    __syncthreads();

    int w = threadIdx.x >> 5, lane = threadIdx.x & 31;
    int l = blockIdx.x*8 + w;
    if (l >= NLINKS) return;

    if (lane == 0) g_counts[l] = 0;     // restore invariant for the next kernel_launch call

    // segment sum over half2 messages: lanes 0-15 take even rows, 16-31 odd rows
    int beg = g_offsets[l], end = g_offsets[l+1];
    const __half2* mb = (const __half2*)g_msgs;
    const int hl = lane & 15, rs = lane >> 4;
    float ax = 0.f, ay = 0.f, bx = 0.f, by = 0.f;
    int i = beg;
    for (; i + 4 <= end; i += 4){
        float2 f0 = __half22float2(mb[(size_t)(i +     rs)*16 + hl]);
        float2 f1 = __half22float2(mb[(size_t)(i + 2 + rs)*16 + hl]);
        ax += f0.x; ay += f0.y; bx += f1.x; by += f1.y;
    }
    for (; i + 2 <= end; i += 2){
        float2 f0 = __half22float2(mb[(size_t)(i + rs)*16 + hl]);
        ax += f0.x; ay += f0.y;
    }
    if (i < end && rs == 0){
        float2 f0 = __half22float2(mb[(size_t)i*16 + hl]);
        ax += f0.x; ay += f0.y;
    }
    ax += bx; ay += by;
    ax += __shfl_xor_sync(0xffffffffu, ax, 16);
    ay += __shfl_xor_sync(0xffffffffu, ay, 16);
    if (lane < 16){ sAgg[w][2*hl] = ax; sAgg[w][2*hl+1] = ay; }

    float hv;
    if (FIRST) hv = (lane == 0) ? __ldg(cap + l) : 0.f;   // initial link state = [cap,0..]
    else       hv = g_link_state[l*HD + lane];
    sH[w][lane] = hv;
    __syncwarp();

    int j = lane;
    float xr = sbi[j], xz = sbi[32+j], xn = sbi[64+j];
    float hr = sbh[j], hz = sbh[32+j], hnv = sbh[64+j];
    #pragma unroll
    for (int k = 0; k < HD; k++){
        float av = sAgg[w][k], hh = sH[w][k];
        xr  += av*sWi[k*G3 + j];
        xz  += av*sWi[k*G3 + 32 + j];
        xn  += av*sWi[k*G3 + 64 + j];
        hr  += hh*sWh[k*G3 + j];
        hz  += hh*sWh[k*G3 + 32 + j];
        hnv += hh*sWh[k*G3 + 64 + j];
    }
    float rr = fsig(xr + hr);
    float zz = fsig(xz + hz);
    float nn = ftanh(xn + rr*hnv);
    float hj = sH[w][j];
    float hnew = nn + zz*(hj - nn);
    g_link_state[l*HD + j] = hnew;

    // next-round path-GRU input transform: gi = hnew @ pWih^T + pbih
    sH2[w][lane] = hnew;
    __syncwarp();
    float g0 = sPB[j], g1 = sPB[32+j], g2 = sPB[64+j];
    #pragma unroll
    for (int k = 0; k < HD; k++){
        float hv2 = sH2[w][k];
        g0 += hv2*sPWT[k*G3 + j];
        g1 += hv2*sPWT[k*G3 + 32 + j];
        g2 += hv2*sPWT[k*G3 + 64 + j];
    }
    g_gi[l*G3 + j]      = g0;
    g_gi[l*G3 + 32 + j] = g1;
    g_gi[l*G3 + 64 + j] = g2;
}

// ---------------- readout MLP ----------------
__global__ void k_read(const float* __restrict__ W1, const float* __restrict__ b1,
                       const float* __restrict__ W2, const float* __restrict__ b2,
                       const float* __restrict__ W3, const float* __restrict__ b3,
                       float* __restrict__ out)
{
    int p = blockIdx.x*blockDim.x + threadIdx.x;
    if (p >= NPATHS) return;
    float h[HD];
    const float4* hp = (const float4*)(g_path_state + p*HD);
    #pragma unroll
    for (int i = 0; i < 8; i++){
        float4 v = hp[i];
        h[4*i] = v.x; h[4*i+1] = v.y; h[4*i+2] = v.z; h[4*i+3] = v.w;
    }
    float x1[8];
    #pragma unroll
    for (int j = 0; j < 8; j++){
        float a = __ldg(b1 + j);
        #pragma unroll
        for (int k = 0; k < HD; k++) a += __ldg(W1 + j*HD + k) * h[k];
        x1[j] = fmaxf(a, 0.f);
    }
    float x2[8];
    #pragma unroll
    for (int j = 0; j < 8; j++){
        float a = __ldg(b2 + j);
        #pragma unroll
        for (int k = 0; k < 8; k++) a += __ldg(W2 + j*8 + k) * x1[k];
        x2[j] = fmaxf(a, 0.f);
    }
    float o = __ldg(b3);
    #pragma unroll
    for (int k = 0; k < 8; k++) o += __ldg(W3 + k) * x2[k];
    out[p] = o;
}

// ---------------- launch ----------------
extern "C" void kernel_launch(void* const* d_in, const int* in_sizes, int n_in,
                              void* d_out, int out_size)
{
    const int*   links = (const int*)  d_in[0];
    const float* cap   = (const float*)d_in[3];
    const float* bw    = (const float*)d_in[4];
    const float* pWih  = (const float*)d_in[5];
    const float* pWhh  = (const float*)d_in[6];
    const float* pbih  = (const float*)d_in[7];
    const float* pbhh  = (const float*)d_in[8];
    const float* lWih  = (const float*)d_in[9];
    const float* lWhh  = (const float*)d_in[10];
    const float* lbih  = (const float*)d_in[11];
    const float* lbhh  = (const float*)d_in[12];
    const float* W1    = (const float*)d_in[13];
    const float* b1    = (const float*)d_in[14];
    const float* W2    = (const float*)d_in[15];
    const float* b2    = (const float*)d_in[16];
    const float* W3    = (const float*)d_in[17];
    const float* b3    = (const float*)d_in[18];
    float* out = (float*)d_out;

    const int nwarps = NPATHS/32;                 // 3125
    const int path_grid = (nwarps + 3)/4;         // 4 warps per 128-thread block
    const int link_grid = (NLINKS + 7)/8;

    // launches 1-3: CSR sort of hop->link (g_counts==0 invariant on entry)
    k_hist<<<(NE + 255)/256, 256>>>(links);
    k_scan<<<1, 256>>>();
    k_pos<<<(NE + 255)/256, 256>>>(links);

    // launch 4 = round-0 k_path (the launch ncu captures)
    k_path<true,true><<<path_grid, 128>>>(links, pWhh, pbhh, pWih, pbih, cap, bw);
    k_linkgi<true><<<link_grid, 256>>>(lWih, lWhh, lbih, lbhh, pWih, pbih, cap);

    for (int t = 1; t < TROUNDS - 1; t++){
        k_path<false,true><<<path_grid, 128>>>(links, pWhh, pbhh, pWih, pbih, cap, bw);
        k_linkgi<false><<<link_grid, 256>>>(lWih, lWhh, lbih, lbhh, pWih, pbih, cap);
    }
    k_path<false,false><<<path_grid, 128>>>(links, pWhh, pbhh, pWih, pbih, cap, bw);
    k_read<<<(NPATHS + 127)/128, 128>>>(W1, b1, W2, b2, W3, b3, out);
}